// round 1
// baseline (speedup 1.0000x reference)
#include <cuda_runtime.h>

#define NB 8
#define NT 2048
#define NC 768
#define HS 64
#define BT (NB*NT)

// log2(e) / sqrt(768)
#define SL2E 0.052058774f

// scratch (device globals: allocation-free rule)
__device__ float g_q[BT*HS];
__device__ float g_k[BT*HS];
__device__ float g_v[BT*HS];

// ---------------------------------------------------------------------------
// QKV projection: one block = 64 rows x 192 cols (Q|K|V), 256 threads.
// Thread tile 4 rows x 12 cols. K-chunks of 16.
// ---------------------------------------------------------------------------
__global__ __launch_bounds__(256) void qkv_kernel(
    const float* __restrict__ x, const float* __restrict__ Wk,
    const float* __restrict__ Wq, const float* __restrict__ Wv)
{
    __shared__ float xs[64][17];    // +1 pad: conflict-free xs[r][kk] reads
    __shared__ float ws[16][192];

    const int row0 = blockIdx.x * 64;
    const int tid  = threadIdx.x;
    const int ty   = tid >> 4;      // 0..15 -> 4 rows each
    const int tx   = tid & 15;      // 0..15 -> 12 cols each

    float acc[4][12];
    #pragma unroll
    for (int i = 0; i < 4; i++)
        #pragma unroll
        for (int j = 0; j < 12; j++) acc[i][j] = 0.f;

    for (int k0 = 0; k0 < NC; k0 += 16) {
        // stage x tile 64x16 (each thread one float4)
        {
            int r  = tid >> 2;
            int c4 = (tid & 3) * 4;
            float4 xv = *reinterpret_cast<const float4*>(&x[(size_t)(row0 + r) * NC + k0 + c4]);
            xs[r][c4+0]=xv.x; xs[r][c4+1]=xv.y; xs[r][c4+2]=xv.z; xs[r][c4+3]=xv.w;
        }
        // stage W tile 16x192: cols [0,64)=Q, [64,128)=K, [128,192)=V
        #pragma unroll
        for (int i = tid; i < 16*48; i += 256) {
            int rr = i / 48;
            int c  = (i % 48) * 4;
            const float* Wp; int cc;
            if (c < 64)       { Wp = Wq; cc = c; }
            else if (c < 128) { Wp = Wk; cc = c - 64; }
            else              { Wp = Wv; cc = c - 128; }
            float4 wv = *reinterpret_cast<const float4*>(&Wp[(size_t)(k0 + rr) * HS + cc]);
            *reinterpret_cast<float4*>(&ws[rr][c]) = wv;
        }
        __syncthreads();

        #pragma unroll
        for (int kk = 0; kk < 16; kk++) {
            float a[4];
            #pragma unroll
            for (int i = 0; i < 4; i++) a[i] = xs[ty*4+i][kk];
            float bv[12];
            #pragma unroll
            for (int j4 = 0; j4 < 3; j4++) {
                float4 w4 = *reinterpret_cast<const float4*>(&ws[kk][tx*12 + j4*4]);
                bv[j4*4+0]=w4.x; bv[j4*4+1]=w4.y; bv[j4*4+2]=w4.z; bv[j4*4+3]=w4.w;
            }
            #pragma unroll
            for (int i = 0; i < 4; i++)
                #pragma unroll
                for (int j = 0; j < 12; j++)
                    acc[i][j] = fmaf(a[i], bv[j], acc[i][j]);
        }
        __syncthreads();
    }

    #pragma unroll
    for (int i = 0; i < 4; i++) {
        size_t r = (size_t)(row0 + ty*4 + i);
        #pragma unroll
        for (int j = 0; j < 12; j++) {
            int c = tx*12 + j;
            float v = acc[i][j];
            if (c < 64)       g_q[r*HS + c]         = v;
            else if (c < 128) g_k[r*HS + (c - 64)]  = v;
            else              g_v[r*HS + (c - 128)] = v;
        }
    }
}

// ---------------------------------------------------------------------------
// Flash attention (causal), fp32. One block = 64 queries, 128 threads.
// Thread grid 8x16: each thread 8 rows x 4 cols for both S and O.
// ---------------------------------------------------------------------------
__global__ __launch_bounds__(128) void attn_kernel(float* __restrict__ out)
{
    extern __shared__ float smem[];
    float (*Qs)[65] = reinterpret_cast<float(*)[65]>(smem);
    float (*Ks)[65] = reinterpret_cast<float(*)[65]>(smem + 64*65);
    float (*Vs)[65] = reinterpret_cast<float(*)[65]>(smem + 2*64*65);
    float (*Ps)[65] = reinterpret_cast<float(*)[65]>(smem + 3*64*65);

    const int b   = blockIdx.y;
    const int qi  = (int)gridDim.x - 1 - (int)blockIdx.x;  // heavy tiles first
    const int tid = threadIdx.x;
    const int ty  = tid >> 4;   // 0..7  -> rows ty*8 .. ty*8+7
    const int tx  = tid & 15;   // 0..15 -> cols tx*4 .. tx*4+3

    const float* qbase = g_q + ((size_t)b*NT + (size_t)qi*64) * HS;

    // stage Q tile
    for (int i = tid; i < 64*16; i += 128) {
        int r = i >> 4; int c4 = (i & 15) * 4;
        float4 v = *reinterpret_cast<const float4*>(&qbase[r*HS + c4]);
        Qs[r][c4+0]=v.x; Qs[r][c4+1]=v.y; Qs[r][c4+2]=v.z; Qs[r][c4+3]=v.w;
    }

    float m[8], l[8], o[8][4];
    #pragma unroll
    for (int i = 0; i < 8; i++) {
        m[i] = -1e30f; l[i] = 0.f;
        #pragma unroll
        for (int j = 0; j < 4; j++) o[i][j] = 0.f;
    }

    for (int jt = 0; jt <= qi; jt++) {
        const float* kptr = g_k + ((size_t)b*NT + (size_t)jt*64) * HS;
        const float* vptr = g_v + ((size_t)b*NT + (size_t)jt*64) * HS;

        __syncthreads();   // prior iter finished reading Ks/Vs/Ps (and Q staged)
        for (int i = tid; i < 64*16; i += 128) {
            int r = i >> 4; int c4 = (i & 15) * 4;
            float4 kv = *reinterpret_cast<const float4*>(&kptr[r*HS + c4]);
            Ks[r][c4+0]=kv.x; Ks[r][c4+1]=kv.y; Ks[r][c4+2]=kv.z; Ks[r][c4+3]=kv.w;
            float4 vv = *reinterpret_cast<const float4*>(&vptr[r*HS + c4]);
            Vs[r][c4+0]=vv.x; Vs[r][c4+1]=vv.y; Vs[r][c4+2]=vv.z; Vs[r][c4+3]=vv.w;
        }
        __syncthreads();

        // S = Q K^T (tile)
        float s[8][4];
        #pragma unroll
        for (int i = 0; i < 8; i++)
            #pragma unroll
            for (int j = 0; j < 4; j++) s[i][j] = 0.f;

        #pragma unroll 8
        for (int k = 0; k < 64; k++) {
            float qv[8];
            #pragma unroll
            for (int i = 0; i < 8; i++) qv[i] = Qs[ty*8+i][k];
            float kv[4];
            #pragma unroll
            for (int j = 0; j < 4; j++) kv[j] = Ks[tx*4+j][k];
            #pragma unroll
            for (int i = 0; i < 8; i++)
                #pragma unroll
                for (int j = 0; j < 4; j++)
                    s[i][j] = fmaf(qv[i], kv[j], s[i][j]);
        }

        // scale to log2 domain + causal mask (only diagonal tile is partial)
        const bool diag = (jt == qi);
        #pragma unroll
        for (int i = 0; i < 8; i++) {
            int qr = qi*64 + ty*8 + i;
            #pragma unroll
            for (int j = 0; j < 4; j++) {
                float t = s[i][j] * SL2E;
                if (diag && (jt*64 + tx*4 + j) > qr) t = -1e30f;
                s[i][j] = t;
            }
        }

        // online softmax update (row groups = 16 lanes, xor-shuffle reduce)
        #pragma unroll
        for (int i = 0; i < 8; i++) {
            float mx = fmaxf(fmaxf(s[i][0], s[i][1]), fmaxf(s[i][2], s[i][3]));
            #pragma unroll
            for (int off = 8; off >= 1; off >>= 1)
                mx = fmaxf(mx, __shfl_xor_sync(0xffffffffu, mx, off));
            float mnew  = fmaxf(m[i], mx);
            float alpha = exp2f(m[i] - mnew);
            float psum = 0.f;
            #pragma unroll
            for (int j = 0; j < 4; j++) {
                float p = exp2f(s[i][j] - mnew);
                s[i][j] = p;
                psum += p;
            }
            #pragma unroll
            for (int off = 8; off >= 1; off >>= 1)
                psum += __shfl_xor_sync(0xffffffffu, psum, off);
            l[i] = l[i]*alpha + psum;
            m[i] = mnew;
            #pragma unroll
            for (int j = 0; j < 4; j++) o[i][j] *= alpha;
        }

        // stage P
        #pragma unroll
        for (int i = 0; i < 8; i++)
            #pragma unroll
            for (int j = 0; j < 4; j++)
                Ps[ty*8+i][tx*4+j] = s[i][j];
        __syncthreads();

        // O += P V (tile)
        #pragma unroll 8
        for (int k = 0; k < 64; k++) {
            float pv[8];
            #pragma unroll
            for (int i = 0; i < 8; i++) pv[i] = Ps[ty*8+i][k];
            float vv[4];
            #pragma unroll
            for (int j = 0; j < 4; j++) vv[j] = Vs[k][tx*4+j];
            #pragma unroll
            for (int i = 0; i < 8; i++)
                #pragma unroll
                for (int j = 0; j < 4; j++)
                    o[i][j] = fmaf(pv[i], vv[j], o[i][j]);
        }
    }

    // normalize + store
    #pragma unroll
    for (int i = 0; i < 8; i++) {
        float inv = 1.0f / l[i];
        size_t r = (size_t)b*NT + (size_t)qi*64 + ty*8 + i;
        float4 ov = make_float4(o[i][0]*inv, o[i][1]*inv, o[i][2]*inv, o[i][3]*inv);
        *reinterpret_cast<float4*>(&out[r*HS + tx*4]) = ov;
    }
}

// ---------------------------------------------------------------------------
extern "C" void kernel_launch(void* const* d_in, const int* in_sizes, int n_in,
                              void* d_out, int out_size)
{
    const float* x  = (const float*)d_in[0];
    const float* Wk = (const float*)d_in[1];
    const float* Wq = (const float*)d_in[2];
    const float* Wv = (const float*)d_in[3];
    float* out = (float*)d_out;

    static bool attr_done = false;
    const int attn_smem = 4 * 64 * 65 * (int)sizeof(float);   // 66560 B
    if (!attr_done) {
        cudaFuncSetAttribute(attn_kernel,
                             cudaFuncAttributeMaxDynamicSharedMemorySize, attn_smem);
        attr_done = true;
    }

    qkv_kernel<<<BT/64, 256>>>(x, Wk, Wq, Wv);
    attn_kernel<<<dim3(NT/64, NB), 128, attn_smem>>>(out);
}

// round 3
// speedup vs baseline: 2.6631x; 2.6631x over previous
#include <cuda_runtime.h>
#include <cuda_bf16.h>

#define NB 8
#define NT 2048
#define NC 768
#define HS 64
#define BT (NB*NT)
// log2(e) / sqrt(768)
#define SL2E 0.0520587735f

typedef unsigned int uint32;

// ---------------- global scratch (allocation-free rule) ----------------
__device__ __align__(16) __nv_bfloat16 g_qh[BT*HS], g_ql[BT*HS];
__device__ __align__(16) __nv_bfloat16 g_kh[BT*HS], g_kl[BT*HS];
__device__ __align__(16) __nv_bfloat16 g_vh[BT*HS], g_vl[BT*HS];
__device__ __align__(16) float g_opart[2][BT*HS];
__device__ float g_lpart[2][BT];

// ---------------- helpers ----------------
__device__ __forceinline__ uint32 smem_u32(const void* p) {
    uint32 a;
    asm("{ .reg .u64 t; cvta.to.shared.u64 t, %1; cvt.u32.u64 %0, t; }" : "=r"(a) : "l"(p));
    return a;
}
__device__ __forceinline__ uint32 sw128(uint32 off) { return off ^ ((off >> 3) & 0x70); }

__device__ __forceinline__ void ldsm4(uint32 addr, uint32* r) {
    asm volatile("ldmatrix.sync.aligned.m8n8.x4.shared.b16 {%0,%1,%2,%3}, [%4];"
                 : "=r"(r[0]), "=r"(r[1]), "=r"(r[2]), "=r"(r[3]) : "r"(addr));
}
__device__ __forceinline__ void ldsm4t(uint32 addr, uint32* r) {
    asm volatile("ldmatrix.sync.aligned.m8n8.x4.trans.shared.b16 {%0,%1,%2,%3}, [%4];"
                 : "=r"(r[0]), "=r"(r[1]), "=r"(r[2]), "=r"(r[3]) : "r"(addr));
}
__device__ __forceinline__ void mma16816(float* c, const uint32* a, uint32 b0, uint32 b1) {
    asm volatile("mma.sync.aligned.m16n8k16.row.col.f32.bf16.bf16.f32 "
                 "{%0,%1,%2,%3}, {%4,%5,%6,%7}, {%8,%9}, {%0,%1,%2,%3};"
                 : "+f"(c[0]), "+f"(c[1]), "+f"(c[2]), "+f"(c[3])
                 : "r"(a[0]), "r"(a[1]), "r"(a[2]), "r"(a[3]), "r"(b0), "r"(b1));
}
__device__ __forceinline__ float ex2(float x) {
    float y; asm("ex2.approx.ftz.f32 %0, %1;" : "=f"(y) : "f"(x)); return y;
}
// split fp32 pair -> bf16x2 hi word + bf16x2 lo (residual) word
__device__ __forceinline__ void split2(float a, float b, uint32& hw, uint32& lw) {
    __nv_bfloat162 h2 = __floats2bfloat162_rn(a, b);
    float ra = a - __bfloat162float(h2.x);
    float rb = b - __bfloat162float(h2.y);
    __nv_bfloat162 l2 = __floats2bfloat162_rn(ra, rb);
    hw = *reinterpret_cast<uint32*>(&h2);
    lw = *reinterpret_cast<uint32*>(&l2);
}

// ===========================================================================
// QKV: per CTA 128 rows x 192 cols (Q|K|V), bf16x3 emulation, 256 threads.
// x tile smem [r][k] swizzled 128B rows; W^T tile smem [k][n] stride 400B.
// ===========================================================================
#define XH 0
#define XL 16384
#define WH 32768
#define WL 58368
#define QKV_SMEM 83968

__global__ __launch_bounds__(256, 1) void qkv_kernel(
    const float* __restrict__ x, const float* __restrict__ Wk,
    const float* __restrict__ Wq, const float* __restrict__ Wv)
{
    extern __shared__ char smem[];
    const uint32 sb = smem_u32(smem);
    const int tid = threadIdx.x;
    const int wid = tid >> 5, lane = tid & 31;
    const int wm = wid & 3, wn = wid >> 2;
    const int row0 = blockIdx.x * 128;

    float c[2][12][4];
    #pragma unroll
    for (int mi = 0; mi < 2; mi++)
        #pragma unroll
        for (int nj = 0; nj < 12; nj++)
            #pragma unroll
            for (int e = 0; e < 4; e++) c[mi][nj][e] = 0.f;

    for (int kc = 0; kc < 12; kc++) {
        if (kc) __syncthreads();
        const int k0 = kc * 64;
        // stage x [128 r x 64 k] -> hi/lo, swizzled
        for (int f = tid; f < 1024; f += 256) {
            int r = f >> 3, g8 = (f & 7) * 8;
            const float* src = x + (size_t)(row0 + r) * NC + k0 + g8;
            float4 v0 = *reinterpret_cast<const float4*>(src);
            float4 v1 = *reinterpret_cast<const float4*>(src + 4);
            uint32 h0, l0, h1, l1, h2, l2, h3, l3;
            split2(v0.x, v0.y, h0, l0); split2(v0.z, v0.w, h1, l1);
            split2(v1.x, v1.y, h2, l2); split2(v1.z, v1.w, h3, l3);
            uint32 off = sw128((uint32)(r * 128 + g8 * 2));
            *reinterpret_cast<uint4*>(smem + XH + off) = make_uint4(h0, h1, h2, h3);
            *reinterpret_cast<uint4*>(smem + XL + off) = make_uint4(l0, l1, l2, l3);
        }
        // stage W^T [64 k x 192 n] -> hi/lo, row stride 400B
        for (int f = tid; f < 3072; f += 256) {
            int kk = f / 48, q = f % 48;
            int n0 = q * 4;
            const float* W = (n0 < 64) ? Wq : (n0 < 128 ? Wk : Wv);
            int nc = n0 & 63;
            float4 w = *reinterpret_cast<const float4*>(&W[(size_t)(k0 + kk) * HS + nc]);
            uint32 h0, l0, h1, l1;
            split2(w.x, w.y, h0, l0); split2(w.z, w.w, h1, l1);
            uint32* wh = reinterpret_cast<uint32*>(smem + WH + kk * 400);
            uint32* wl = reinterpret_cast<uint32*>(smem + WL + kk * 400);
            wh[(n0 >> 1)] = h0; wh[(n0 >> 1) + 1] = h1;
            wl[(n0 >> 1)] = l0; wl[(n0 >> 1) + 1] = l1;
        }
        __syncthreads();

        #pragma unroll
        for (int ks = 0; ks < 4; ks++) {
            uint32 Ah[2][4], Al[2][4];
            #pragma unroll
            for (int mi = 0; mi < 2; mi++) {
                uint32 off = sw128((uint32)((wm * 32 + mi * 16 + (lane & 15)) * 128
                                            + ks * 32 + (lane >> 4) * 16));
                ldsm4(sb + XH + off, Ah[mi]);
                ldsm4(sb + XL + off, Al[mi]);
            }
            #pragma unroll
            for (int njp = 0; njp < 6; njp++) {
                int nabs = wn * 96 + njp * 16 + ((lane >> 4) & 1) * 8;
                int kl_ = ks * 16 + (lane & 15);
                uint32 boff = (uint32)(kl_ * 400 + nabs * 2);
                uint32 Bh[4], Bl[4];
                ldsm4t(sb + WH + boff, Bh);
                ldsm4t(sb + WL + boff, Bl);
                #pragma unroll
                for (int mi = 0; mi < 2; mi++)
                    #pragma unroll
                    for (int j = 0; j < 2; j++) {
                        float* cc = c[mi][njp * 2 + j];
                        mma16816(cc, Ah[mi], Bh[2*j], Bh[2*j+1]);
                        mma16816(cc, Ah[mi], Bl[2*j], Bl[2*j+1]);
                        mma16816(cc, Al[mi], Bh[2*j], Bh[2*j+1]);
                    }
            }
        }
    }

    // epilogue: write q (pre-scaled), k, v hi/lo pairs
    const int g = lane >> 2, t = lane & 3;
    uint32* gqh = reinterpret_cast<uint32*>(g_qh);
    uint32* gql = reinterpret_cast<uint32*>(g_ql);
    uint32* gkh = reinterpret_cast<uint32*>(g_kh);
    uint32* gkl = reinterpret_cast<uint32*>(g_kl);
    uint32* gvh = reinterpret_cast<uint32*>(g_vh);
    uint32* gvl = reinterpret_cast<uint32*>(g_vl);
    #pragma unroll
    for (int mi = 0; mi < 2; mi++)
        #pragma unroll
        for (int nj = 0; nj < 12; nj++)
            #pragma unroll
            for (int h = 0; h < 2; h++) {
                size_t row = (size_t)(row0 + wm * 32 + mi * 16 + h * 8 + g);
                int colp = wn * 48 + nj * 4 + t;   // bf16x2 pair index 0..95
                float v0 = c[mi][nj][h * 2], v1 = c[mi][nj][h * 2 + 1];
                if (colp < 32) { v0 *= SL2E; v1 *= SL2E; }
                uint32 hw, lw;
                split2(v0, v1, hw, lw);
                if (colp < 32)      { gqh[row * 32 + colp]      = hw; gql[row * 32 + colp]      = lw; }
                else if (colp < 64) { gkh[row * 32 + colp - 32] = hw; gkl[row * 32 + colp - 32] = lw; }
                else                { gvh[row * 32 + colp - 64] = hw; gvl[row * 32 + colp - 64] = lw; }
            }
}

// ===========================================================================
// Attention: unit = (b, 128-query tile, key split). 256 threads, 8 warps.
// warp = 32 q-rows (wm) x 64 keys (wk). P stays in registers.
// ===========================================================================
#define AQH 0
#define AQL 16384
#define AKH 32768
#define AKL 49152
#define AVH 65536
#define AVL 81920
#define AOB 32768          /* O scratch overlay (128 x stride66 fp32) */
#define ALB 66560          /* l scratch overlay (2 x 128 fp32)        */
#define ATTN_SMEM 98304

__global__ __launch_bounds__(256, 1) void attn_kernel()
{
    extern __shared__ char smem[];
    const uint32 sb = smem_u32(smem);
    const int tid = threadIdx.x;
    const int wid = tid >> 5, lane = tid & 31;
    const int wm = wid & 3, wk = wid >> 2;
    const int g = lane >> 2, t = lane & 3;

    // unit decode (heavy-first)
    const int uid = blockIdx.x;
    const int b = uid & 7;
    const int rr_ = 23 - (uid >> 3);
    int qi, s;
    int kb, ke;
    if (rr_ < 8) { qi = rr_; s = 0; kb = 0; ke = qi + 1; }
    else {
        qi = 8 + ((rr_ - 8) >> 1); s = (rr_ - 8) & 1;
        int half = (qi + 1) >> 1;
        kb = s ? half : 0;
        ke = s ? qi + 1 : half;
    }

    const uint32* gqh = reinterpret_cast<const uint32*>(g_qh);
    const uint32* gql = reinterpret_cast<const uint32*>(g_ql);
    const uint32* gkh = reinterpret_cast<const uint32*>(g_kh);
    const uint32* gkl = reinterpret_cast<const uint32*>(g_kl);
    const uint32* gvh = reinterpret_cast<const uint32*>(g_vh);
    const uint32* gvl = reinterpret_cast<const uint32*>(g_vl);

    // stage Q tile
    {
        size_t base = ((size_t)b * NT + (size_t)qi * 128) * 32;
        for (int f = tid; f < 4096; f += 256) {
            int r = f >> 5, cw = f & 31;
            uint32 off = sw128((uint32)(r * 128 + cw * 4));
            *reinterpret_cast<uint32*>(smem + AQH + off) = gqh[base + r * 32 + cw];
            *reinterpret_cast<uint32*>(smem + AQL + off) = gql[base + r * 32 + cw];
        }
    }

    float o[2][8][4];
    float lsum[2][2];
    #pragma unroll
    for (int mi = 0; mi < 2; mi++) {
        lsum[mi][0] = 0.f; lsum[mi][1] = 0.f;
        #pragma unroll
        for (int nj = 0; nj < 8; nj++)
            #pragma unroll
            for (int e = 0; e < 4; e++) o[mi][nj][e] = 0.f;
    }

    for (int jt = kb; jt < ke; jt++) {
        if (jt != kb) __syncthreads();
        // stage K, V tiles
        {
            size_t base = ((size_t)b * NT + (size_t)jt * 128) * 32;
            for (int f = tid; f < 4096; f += 256) {
                int r = f >> 5, cw = f & 31;
                uint32 off = sw128((uint32)(r * 128 + cw * 4));
                size_t gidx = base + r * 32 + cw;
                *reinterpret_cast<uint32*>(smem + AKH + off) = gkh[gidx];
                *reinterpret_cast<uint32*>(smem + AKL + off) = gkl[gidx];
                *reinterpret_cast<uint32*>(smem + AVH + off) = gvh[gidx];
                *reinterpret_cast<uint32*>(smem + AVL + off) = gvl[gidx];
            }
        }
        __syncthreads();

        // ---- S = Q K^T ----
        float sS[2][8][4];
        #pragma unroll
        for (int mi = 0; mi < 2; mi++)
            #pragma unroll
            for (int nj = 0; nj < 8; nj++)
                #pragma unroll
                for (int e = 0; e < 4; e++) sS[mi][nj][e] = 0.f;

        #pragma unroll
        for (int ks = 0; ks < 4; ks++) {
            uint32 Qh[2][4], Ql[2][4];
            #pragma unroll
            for (int mi = 0; mi < 2; mi++) {
                uint32 off = sw128((uint32)((wm * 32 + mi * 16 + (lane & 15)) * 128
                                            + ks * 32 + (lane >> 4) * 16));
                ldsm4(sb + AQH + off, Qh[mi]);
                ldsm4(sb + AQL + off, Ql[mi]);
            }
            #pragma unroll
            for (int njp = 0; njp < 4; njp++) {
                int row = wk * 64 + njp * 16 + (lane & 7) + ((lane >> 4) & 1) * 8;
                uint32 off = sw128((uint32)(row * 128 + ks * 32 + ((lane >> 3) & 1) * 16));
                uint32 Kh[4], Kl[4];
                ldsm4(sb + AKH + off, Kh);
                ldsm4(sb + AKL + off, Kl);
                #pragma unroll
                for (int mi = 0; mi < 2; mi++)
                    #pragma unroll
                    for (int j = 0; j < 2; j++) {
                        float* cc = sS[mi][njp * 2 + j];
                        mma16816(cc, Qh[mi], Kh[2*j], Kh[2*j+1]);
                        mma16816(cc, Qh[mi], Kl[2*j], Kl[2*j+1]);
                        mma16816(cc, Ql[mi], Kh[2*j], Kh[2*j+1]);
                    }
            }
        }

        // ---- epilogue: mask + exp2 + row-sum + pack P frags ----
        const bool diag = (jt == qi);
        #pragma unroll
        for (int mi = 0; mi < 2; mi++)
            #pragma unroll
            for (int nj = 0; nj < 8; nj++)
                #pragma unroll
                for (int e = 0; e < 4; e++) {
                    int rl = wm * 32 + mi * 16 + (e >> 1) * 8 + g;
                    int cl = wk * 64 + nj * 8 + 2 * t + (e & 1);
                    float p = (diag && cl > rl) ? 0.f : ex2(sS[mi][nj][e]);
                    sS[mi][nj][e] = p;
                    lsum[mi][e >> 1] += p;
                }
        uint32 aPh[2][4][4], aPl[2][4][4];
        #pragma unroll
        for (int mi = 0; mi < 2; mi++)
            #pragma unroll
            for (int kc = 0; kc < 4; kc++) {
                split2(sS[mi][2*kc][0],   sS[mi][2*kc][1],   aPh[mi][kc][0], aPl[mi][kc][0]);
                split2(sS[mi][2*kc][2],   sS[mi][2*kc][3],   aPh[mi][kc][1], aPl[mi][kc][1]);
                split2(sS[mi][2*kc+1][0], sS[mi][2*kc+1][1], aPh[mi][kc][2], aPl[mi][kc][2]);
                split2(sS[mi][2*kc+1][2], sS[mi][2*kc+1][3], aPh[mi][kc][3], aPl[mi][kc][3]);
            }

        // ---- O += P V ----
        #pragma unroll
        for (int kc = 0; kc < 4; kc++)
            #pragma unroll
            for (int njp = 0; njp < 4; njp++) {
                int kr = wk * 64 + kc * 16 + (lane & 15);
                int nn = njp * 16 + ((lane >> 4) & 1) * 8;
                uint32 off = sw128((uint32)(kr * 128 + nn * 2));
                uint32 Vh[4], Vl[4];
                ldsm4t(sb + AVH + off, Vh);
                ldsm4t(sb + AVL + off, Vl);
                #pragma unroll
                for (int mi = 0; mi < 2; mi++)
                    #pragma unroll
                    for (int j = 0; j < 2; j++) {
                        float* oo = o[mi][njp * 2 + j];
                        mma16816(oo, aPh[mi][kc], Vh[2*j], Vh[2*j+1]);
                        mma16816(oo, aPh[mi][kc], Vl[2*j], Vl[2*j+1]);
                        mma16816(oo, aPl[mi][kc], Vh[2*j], Vh[2*j+1]);
                    }
            }
    }

    // ---- reductions & store ----
    #pragma unroll
    for (int mi = 0; mi < 2; mi++)
        #pragma unroll
        for (int h = 0; h < 2; h++) {
            float v = lsum[mi][h];
            v += __shfl_xor_sync(0xffffffffu, v, 1);
            v += __shfl_xor_sync(0xffffffffu, v, 2);
            lsum[mi][h] = v;
        }

    __syncthreads();   // everyone done reading K/V smem; overlay scratch
    float* Obuf = reinterpret_cast<float*>(smem + AOB);
    float* lbuf = reinterpret_cast<float*>(smem + ALB);

    if (t == 0) {
        #pragma unroll
        for (int mi = 0; mi < 2; mi++)
            #pragma unroll
            for (int h = 0; h < 2; h++)
                lbuf[wk * 128 + wm * 32 + mi * 16 + h * 8 + g] = lsum[mi][h];
    }
    if (wk == 1) {
        #pragma unroll
        for (int mi = 0; mi < 2; mi++)
            #pragma unroll
            for (int nj = 0; nj < 8; nj++) {
                int r0 = wm * 32 + mi * 16 + g;
                int col = nj * 8 + 2 * t;
                *reinterpret_cast<float2*>(&Obuf[r0 * 66 + col])
                    = make_float2(o[mi][nj][0], o[mi][nj][1]);
                *reinterpret_cast<float2*>(&Obuf[(r0 + 8) * 66 + col])
                    = make_float2(o[mi][nj][2], o[mi][nj][3]);
            }
    }
    __syncthreads();

    const size_t qbase = (size_t)b * NT + (size_t)qi * 128;
    if (wk == 0) {
        float* op = g_opart[s];
        #pragma unroll
        for (int mi = 0; mi < 2; mi++)
            #pragma unroll
            for (int nj = 0; nj < 8; nj++) {
                int r0 = wm * 32 + mi * 16 + g;
                int col = nj * 8 + 2 * t;
                float2 u0 = *reinterpret_cast<float2*>(&Obuf[r0 * 66 + col]);
                float2 u1 = *reinterpret_cast<float2*>(&Obuf[(r0 + 8) * 66 + col]);
                *reinterpret_cast<float2*>(&op[(qbase + r0) * 64 + col])
                    = make_float2(o[mi][nj][0] + u0.x, o[mi][nj][1] + u0.y);
                *reinterpret_cast<float2*>(&op[(qbase + r0 + 8) * 64 + col])
                    = make_float2(o[mi][nj][2] + u1.x, o[mi][nj][3] + u1.y);
            }
    }
    if (tid < 128)
        g_lpart[s][qbase + tid] = lbuf[tid] + lbuf[128 + tid];
}

// ===========================================================================
// Combine: out = (O0 [+ O1]) / (l0 [+ l1])
// ===========================================================================
__global__ __launch_bounds__(256) void combine_kernel(float* __restrict__ out)
{
    int f = blockIdx.x * 256 + threadIdx.x;   // float4 index
    int row = f >> 4;
    int qi = (row & (NT - 1)) >> 7;
    float l = g_lpart[0][row];
    float4 o = reinterpret_cast<const float4*>(g_opart[0])[f];
    if (qi >= 8) {
        l += g_lpart[1][row];
        float4 o1 = reinterpret_cast<const float4*>(g_opart[1])[f];
        o.x += o1.x; o.y += o1.y; o.z += o1.z; o.w += o1.w;
    }
    float inv = 1.0f / l;
    o.x *= inv; o.y *= inv; o.z *= inv; o.w *= inv;
    reinterpret_cast<float4*>(out)[f] = o;
}

// ===========================================================================
extern "C" void kernel_launch(void* const* d_in, const int* in_sizes, int n_in,
                              void* d_out, int out_size)
{
    const float* x  = (const float*)d_in[0];
    const float* Wk = (const float*)d_in[1];
    const float* Wq = (const float*)d_in[2];
    const float* Wv = (const float*)d_in[3];
    float* out = (float*)d_out;

    static bool attr_done = false;
    if (!attr_done) {
        cudaFuncSetAttribute(qkv_kernel,  cudaFuncAttributeMaxDynamicSharedMemorySize, QKV_SMEM);
        cudaFuncSetAttribute(attn_kernel, cudaFuncAttributeMaxDynamicSharedMemorySize, ATTN_SMEM);
        attr_done = true;
    }

    qkv_kernel<<<BT / 128, 256, QKV_SMEM>>>(x, Wk, Wq, Wv);
    attn_kernel<<<192, 256, ATTN_SMEM>>>();
    combine_kernel<<<(BT * HS / 4) / 256, 256>>>(out);
}

// round 4
// speedup vs baseline: 3.8461x; 1.4442x over previous
#include <cuda_runtime.h>
#include <cuda_bf16.h>

#define NB 8
#define NT 2048
#define NC 768
#define HS 64
#define BT (NB*NT)
// log2(e) / sqrt(768)
#define SL2E 0.0520587735f

typedef unsigned int uint32;

// ---------------- global scratch (allocation-free rule) ----------------
__device__ __align__(16) __nv_bfloat16 g_qh[BT*HS], g_ql[BT*HS];
__device__ __align__(16) __nv_bfloat16 g_kh[BT*HS], g_kl[BT*HS];
__device__ __align__(16) __nv_bfloat16 g_vh[BT*HS], g_vl[BT*HS];
__device__ __align__(16) uint32 g_wh[768*96], g_wl[768*96];   // W^T pre-split, [k][n-pair]
__device__ __align__(16) float g_opart[2][BT*HS];
__device__ float g_lpart[2][BT];

// ---------------- helpers ----------------
__device__ __forceinline__ uint32 smem_u32(const void* p) {
    uint32 a;
    asm("{ .reg .u64 t; cvta.to.shared.u64 t, %1; cvt.u32.u64 %0, t; }" : "=r"(a) : "l"(p));
    return a;
}
__device__ __forceinline__ uint32 sw128(uint32 off) { return off ^ ((off >> 3) & 0x70); }

__device__ __forceinline__ void ldsm4(uint32 addr, uint32* r) {
    asm volatile("ldmatrix.sync.aligned.m8n8.x4.shared.b16 {%0,%1,%2,%3}, [%4];"
                 : "=r"(r[0]), "=r"(r[1]), "=r"(r[2]), "=r"(r[3]) : "r"(addr));
}
__device__ __forceinline__ void ldsm4t(uint32 addr, uint32* r) {
    asm volatile("ldmatrix.sync.aligned.m8n8.x4.trans.shared.b16 {%0,%1,%2,%3}, [%4];"
                 : "=r"(r[0]), "=r"(r[1]), "=r"(r[2]), "=r"(r[3]) : "r"(addr));
}
__device__ __forceinline__ void mma16816(float* c, const uint32* a, uint32 b0, uint32 b1) {
    asm volatile("mma.sync.aligned.m16n8k16.row.col.f32.bf16.bf16.f32 "
                 "{%0,%1,%2,%3}, {%4,%5,%6,%7}, {%8,%9}, {%0,%1,%2,%3};"
                 : "+f"(c[0]), "+f"(c[1]), "+f"(c[2]), "+f"(c[3])
                 : "r"(a[0]), "r"(a[1]), "r"(a[2]), "r"(a[3]), "r"(b0), "r"(b1));
}
__device__ __forceinline__ float ex2(float x) {
    float y; asm("ex2.approx.ftz.f32 %0, %1;" : "=f"(y) : "f"(x)); return y;
}
__device__ __forceinline__ void split2(float a, float b, uint32& hw, uint32& lw) {
    __nv_bfloat162 h2 = __floats2bfloat162_rn(a, b);
    float ra = a - __bfloat162float(h2.x);
    float rb = b - __bfloat162float(h2.y);
    __nv_bfloat162 l2 = __floats2bfloat162_rn(ra, rb);
    hw = *reinterpret_cast<uint32*>(&h2);
    lw = *reinterpret_cast<uint32*>(&l2);
}
#define CP_ASYNC16(dst, src) \
    asm volatile("cp.async.cg.shared.global [%0], [%1], 16;" :: "r"(dst), "l"(src) : "memory")
#define CP_COMMIT asm volatile("cp.async.commit_group;" ::: "memory")
#define CP_WAIT0  asm volatile("cp.async.wait_group 0;" ::: "memory")

// ===========================================================================
// W pre-split: gw[k][n] for n in [0,192) = [Wq|Wk|Wv] columns, bf16 hi/lo pairs
// ===========================================================================
__global__ __launch_bounds__(256) void wsplit_kernel(
    const float* __restrict__ Wk, const float* __restrict__ Wq, const float* __restrict__ Wv)
{
    int i = blockIdx.x * 256 + threadIdx.x;   // 768*96 = 73728 pair slots
    int k = i / 96, p = i % 96;
    int n0 = p * 2;
    const float* W = (n0 < 64) ? Wq : (n0 < 128 ? Wk : Wv);
    int nc = n0 & 63;
    float a = W[(size_t)k * HS + nc], b = W[(size_t)k * HS + nc + 1];
    uint32 hw, lw;
    split2(a, b, hw, lw);
    g_wh[i] = hw; g_wl[i] = lw;
}

// ===========================================================================
// QKV: per CTA 128 rows x 192 cols, bf16x3, 2-stage pipelined. 256 threads.
// Stage layout: XH=0(16K) XL=16K WH=32K(25.6K stride400) WL=58368
// ===========================================================================
#define XH 0
#define XL 16384
#define WH 32768
#define WL 58368
#define QSTG 83968
#define QKV_SMEM (2*QSTG)

__global__ __launch_bounds__(256, 1) void qkv_kernel(const float* __restrict__ x)
{
    extern __shared__ char smem[];
    const uint32 sb = smem_u32(smem);
    const int tid = threadIdx.x;
    const int wid = tid >> 5, lane = tid & 31;
    const int wm = wid & 3, wn = wid >> 2;
    const int row0 = blockIdx.x * 128;

    float c[2][12][4];
    #pragma unroll
    for (int mi = 0; mi < 2; mi++)
        #pragma unroll
        for (int nj = 0; nj < 12; nj++)
            #pragma unroll
            for (int e = 0; e < 4; e++) c[mi][nj][e] = 0.f;

    float4 rx[4][2];

    // ---- prologue: chunk 0 ----
    {
        const int k0 = 0;
        #pragma unroll
        for (int i = 0; i < 4; i++) {
            int f = tid + i * 256, r = f >> 3, g8 = (f & 7) * 8;
            const float* src = x + (size_t)(row0 + r) * NC + k0 + g8;
            rx[i][0] = *reinterpret_cast<const float4*>(src);
            rx[i][1] = *reinterpret_cast<const float4*>(src + 4);
        }
        #pragma unroll
        for (int i = 0; i < 6; i++) {
            int f = tid + i * 256, kk = f / 24, cc = f % 24;
            CP_ASYNC16(sb + WH + kk * 400 + cc * 16, &g_wh[(size_t)(k0 + kk) * 96 + cc * 4]);
            CP_ASYNC16(sb + WL + kk * 400 + cc * 16, &g_wl[(size_t)(k0 + kk) * 96 + cc * 4]);
        }
        CP_COMMIT;
        #pragma unroll
        for (int i = 0; i < 4; i++) {
            int f = tid + i * 256, r = f >> 3, g8 = (f & 7) * 8;
            uint32 h0, l0, h1, l1, h2, l2, h3, l3;
            split2(rx[i][0].x, rx[i][0].y, h0, l0); split2(rx[i][0].z, rx[i][0].w, h1, l1);
            split2(rx[i][1].x, rx[i][1].y, h2, l2); split2(rx[i][1].z, rx[i][1].w, h3, l3);
            uint32 off = sw128((uint32)(r * 128 + g8 * 2));
            *reinterpret_cast<uint4*>(smem + XH + off) = make_uint4(h0, h1, h2, h3);
            *reinterpret_cast<uint4*>(smem + XL + off) = make_uint4(l0, l1, l2, l3);
        }
    }

    for (int kc = 0; kc < 12; kc++) {
        char* cur = smem + (kc & 1) * QSTG;
        const uint32 stb = sb + (kc & 1) * QSTG;
        char* nxt = smem + ((kc + 1) & 1) * QSTG;
        const uint32 stbn = sb + ((kc + 1) & 1) * QSTG;

        CP_WAIT0;
        __syncthreads();

        if (kc < 11) {
            const int k0 = (kc + 1) * 64;
            #pragma unroll
            for (int i = 0; i < 4; i++) {
                int f = tid + i * 256, r = f >> 3, g8 = (f & 7) * 8;
                const float* src = x + (size_t)(row0 + r) * NC + k0 + g8;
                rx[i][0] = *reinterpret_cast<const float4*>(src);
                rx[i][1] = *reinterpret_cast<const float4*>(src + 4);
            }
            #pragma unroll
            for (int i = 0; i < 6; i++) {
                int f = tid + i * 256, kk = f / 24, cc = f % 24;
                CP_ASYNC16(stbn + WH + kk * 400 + cc * 16, &g_wh[(size_t)(k0 + kk) * 96 + cc * 4]);
                CP_ASYNC16(stbn + WL + kk * 400 + cc * 16, &g_wl[(size_t)(k0 + kk) * 96 + cc * 4]);
            }
            CP_COMMIT;
        }

        // ---- MMA phase on cur ----
        #pragma unroll
        for (int ks = 0; ks < 4; ks++) {
            uint32 Ah[2][4], Al[2][4];
            #pragma unroll
            for (int mi = 0; mi < 2; mi++) {
                uint32 off = sw128((uint32)((wm * 32 + mi * 16 + (lane & 15)) * 128
                                            + ks * 32 + (lane >> 4) * 16));
                ldsm4(stb + XH + off, Ah[mi]);
                ldsm4(stb + XL + off, Al[mi]);
            }
            #pragma unroll
            for (int njp = 0; njp < 6; njp++) {
                int nabs = wn * 96 + njp * 16 + ((lane >> 4) & 1) * 8;
                int kl_ = ks * 16 + (lane & 15);
                uint32 boff = (uint32)(kl_ * 400 + nabs * 2);
                uint32 Bh[4], Bl[4];
                ldsm4t(stb + WH + boff, Bh);
                ldsm4t(stb + WL + boff, Bl);
                #pragma unroll
                for (int mi = 0; mi < 2; mi++)
                    #pragma unroll
                    for (int j = 0; j < 2; j++) {
                        float* cc = c[mi][njp * 2 + j];
                        mma16816(cc, Ah[mi], Bh[2*j], Bh[2*j+1]);
                        mma16816(cc, Ah[mi], Bl[2*j], Bl[2*j+1]);
                        mma16816(cc, Al[mi], Bh[2*j], Bh[2*j+1]);
                    }
            }
        }

        if (kc < 11) {
            #pragma unroll
            for (int i = 0; i < 4; i++) {
                int f = tid + i * 256, r = f >> 3, g8 = (f & 7) * 8;
                uint32 h0, l0, h1, l1, h2, l2, h3, l3;
                split2(rx[i][0].x, rx[i][0].y, h0, l0); split2(rx[i][0].z, rx[i][0].w, h1, l1);
                split2(rx[i][1].x, rx[i][1].y, h2, l2); split2(rx[i][1].z, rx[i][1].w, h3, l3);
                uint32 off = sw128((uint32)(r * 128 + g8 * 2));
                *reinterpret_cast<uint4*>(nxt + XH + off) = make_uint4(h0, h1, h2, h3);
                *reinterpret_cast<uint4*>(nxt + XL + off) = make_uint4(l0, l1, l2, l3);
            }
        }
    }

    // ---- epilogue: write q (pre-scaled), k, v hi/lo pairs ----
    const int g = lane >> 2, t = lane & 3;
    uint32* gqh = reinterpret_cast<uint32*>(g_qh);
    uint32* gql = reinterpret_cast<uint32*>(g_ql);
    uint32* gkh = reinterpret_cast<uint32*>(g_kh);
    uint32* gkl = reinterpret_cast<uint32*>(g_kl);
    uint32* gvh = reinterpret_cast<uint32*>(g_vh);
    uint32* gvl = reinterpret_cast<uint32*>(g_vl);
    #pragma unroll
    for (int mi = 0; mi < 2; mi++)
        #pragma unroll
        for (int nj = 0; nj < 12; nj++)
            #pragma unroll
            for (int h = 0; h < 2; h++) {
                size_t row = (size_t)(row0 + wm * 32 + mi * 16 + h * 8 + g);
                int colp = wn * 48 + nj * 4 + t;
                float v0 = c[mi][nj][h * 2], v1 = c[mi][nj][h * 2 + 1];
                if (colp < 32) { v0 *= SL2E; v1 *= SL2E; }
                uint32 hw, lw;
                split2(v0, v1, hw, lw);
                if (colp < 32)      { gqh[row * 32 + colp]      = hw; gql[row * 32 + colp]      = lw; }
                else if (colp < 64) { gkh[row * 32 + colp - 32] = hw; gkl[row * 32 + colp - 32] = lw; }
                else                { gvh[row * 32 + colp - 64] = hw; gvl[row * 32 + colp - 64] = lw; }
            }
}

// ===========================================================================
// Attention: unit = (b, 128-query tile, key split). 256 threads, 8 warps.
// K/V double-buffered via cp.async. warp = 32 q-rows x 64 keys.
// ===========================================================================
#define AQH 0
#define AQL 16384
#define AST 32768
#define STG 65536
#define KH_ 0
#define KL_ 16384
#define VH_ 32768
#define VL_ 49152
#define AOB 32768          /* overlay on stage 0 after final barrier */
#define ALB 66560
#define ATTN_SMEM (AST + 2*STG)

__device__ __forceinline__ void stage_kv_async(uint32 dstb, int b, int jt, int tid)
{
    const uint32* gkh = reinterpret_cast<const uint32*>(g_kh);
    const uint32* gkl = reinterpret_cast<const uint32*>(g_kl);
    const uint32* gvh = reinterpret_cast<const uint32*>(g_vh);
    const uint32* gvl = reinterpret_cast<const uint32*>(g_vl);
    size_t base = ((size_t)b * NT + (size_t)jt * 128) * 32;
    #pragma unroll
    for (int i = 0; i < 4; i++) {
        int f = tid + i * 256;              // 1024 16B-chunks per array
        int r = f >> 3, c16 = f & 7;
        uint32 off = sw128((uint32)(r * 128 + c16 * 16));
        size_t gidx = base + r * 32 + c16 * 4;
        CP_ASYNC16(dstb + KH_ + off, gkh + gidx);
        CP_ASYNC16(dstb + KL_ + off, gkl + gidx);
        CP_ASYNC16(dstb + VH_ + off, gvh + gidx);
        CP_ASYNC16(dstb + VL_ + off, gvl + gidx);
    }
}

__global__ __launch_bounds__(256, 1) void attn_kernel()
{
    extern __shared__ char smem[];
    const uint32 sb = smem_u32(smem);
    const int tid = threadIdx.x;
    const int wid = tid >> 5, lane = tid & 31;
    const int wm = wid & 3, wk = wid >> 2;
    const int g = lane >> 2, t = lane & 3;

    // unit decode (heavy-first)
    const int uid = blockIdx.x;
    const int b = uid & 7;
    const int rr_ = 23 - (uid >> 3);
    int qi, s, kb, ke;
    if (rr_ < 8) { qi = rr_; s = 0; kb = 0; ke = qi + 1; }
    else {
        qi = 8 + ((rr_ - 8) >> 1); s = (rr_ - 8) & 1;
        int half = (qi + 1) >> 1;
        kb = s ? half : 0;
        ke = s ? qi + 1 : half;
    }

    // prologue: async stage first K/V tile, plain-stage Q tile
    stage_kv_async(sb + AST, b, kb, tid);
    CP_COMMIT;
    {
        const uint32* gqh = reinterpret_cast<const uint32*>(g_qh);
        const uint32* gql = reinterpret_cast<const uint32*>(g_ql);
        size_t base = ((size_t)b * NT + (size_t)qi * 128) * 32;
        for (int f = tid; f < 4096; f += 256) {
            int r = f >> 5, cw = f & 31;
            uint32 off = sw128((uint32)(r * 128 + cw * 4));
            *reinterpret_cast<uint32*>(smem + AQH + off) = gqh[base + r * 32 + cw];
            *reinterpret_cast<uint32*>(smem + AQL + off) = gql[base + r * 32 + cw];
        }
    }

    float o[2][8][4];
    float lsum[2][2];
    #pragma unroll
    for (int mi = 0; mi < 2; mi++) {
        lsum[mi][0] = 0.f; lsum[mi][1] = 0.f;
        #pragma unroll
        for (int nj = 0; nj < 8; nj++)
            #pragma unroll
            for (int e = 0; e < 4; e++) o[mi][nj][e] = 0.f;
    }

    for (int jt = kb; jt < ke; jt++) {
        const int p = (jt - kb) & 1;
        const uint32 stb = sb + AST + p * STG;

        CP_WAIT0;
        __syncthreads();

        if (jt + 1 < ke) {
            stage_kv_async(sb + AST + (p ^ 1) * STG, b, jt + 1, tid);
            CP_COMMIT;
        }

        // ---- S = Q K^T ----
        float sS[2][8][4];
        #pragma unroll
        for (int mi = 0; mi < 2; mi++)
            #pragma unroll
            for (int nj = 0; nj < 8; nj++)
                #pragma unroll
                for (int e = 0; e < 4; e++) sS[mi][nj][e] = 0.f;

        #pragma unroll
        for (int ks = 0; ks < 4; ks++) {
            uint32 Qh[2][4], Ql[2][4];
            #pragma unroll
            for (int mi = 0; mi < 2; mi++) {
                uint32 off = sw128((uint32)((wm * 32 + mi * 16 + (lane & 15)) * 128
                                            + ks * 32 + (lane >> 4) * 16));
                ldsm4(sb + AQH + off, Qh[mi]);
                ldsm4(sb + AQL + off, Ql[mi]);
            }
            #pragma unroll
            for (int njp = 0; njp < 4; njp++) {
                int row = wk * 64 + njp * 16 + (lane & 7) + ((lane >> 4) & 1) * 8;
                uint32 off = sw128((uint32)(row * 128 + ks * 32 + ((lane >> 3) & 1) * 16));
                uint32 Kh[4], Kl[4];
                ldsm4(stb + KH_ + off, Kh);
                ldsm4(stb + KL_ + off, Kl);
                #pragma unroll
                for (int mi = 0; mi < 2; mi++)
                    #pragma unroll
                    for (int j = 0; j < 2; j++) {
                        float* cc = sS[mi][njp * 2 + j];
                        mma16816(cc, Qh[mi], Kh[2*j], Kh[2*j+1]);
                        mma16816(cc, Qh[mi], Kl[2*j], Kl[2*j+1]);
                        mma16816(cc, Ql[mi], Kh[2*j], Kh[2*j+1]);
                    }
            }
        }

        // ---- epilogue: mask + exp2 + row-sum + pack P frags ----
        const bool diag = (jt == qi);
        #pragma unroll
        for (int mi = 0; mi < 2; mi++)
            #pragma unroll
            for (int nj = 0; nj < 8; nj++)
                #pragma unroll
                for (int e = 0; e < 4; e++) {
                    int rl = wm * 32 + mi * 16 + (e >> 1) * 8 + g;
                    int cl = wk * 64 + nj * 8 + 2 * t + (e & 1);
                    float p2 = (diag && cl > rl) ? 0.f : ex2(sS[mi][nj][e]);
                    sS[mi][nj][e] = p2;
                    lsum[mi][e >> 1] += p2;
                }
        uint32 aPh[2][4][4], aPl[2][4][4];
        #pragma unroll
        for (int mi = 0; mi < 2; mi++)
            #pragma unroll
            for (int kc = 0; kc < 4; kc++) {
                split2(sS[mi][2*kc][0],   sS[mi][2*kc][1],   aPh[mi][kc][0], aPl[mi][kc][0]);
                split2(sS[mi][2*kc][2],   sS[mi][2*kc][3],   aPh[mi][kc][1], aPl[mi][kc][1]);
                split2(sS[mi][2*kc+1][0], sS[mi][2*kc+1][1], aPh[mi][kc][2], aPl[mi][kc][2]);
                split2(sS[mi][2*kc+1][2], sS[mi][2*kc+1][3], aPh[mi][kc][3], aPl[mi][kc][3]);
            }

        // ---- O += P V ----
        #pragma unroll
        for (int kc = 0; kc < 4; kc++)
            #pragma unroll
            for (int njp = 0; njp < 4; njp++) {
                int kr = wk * 64 + kc * 16 + (lane & 15);
                int nn = njp * 16 + ((lane >> 4) & 1) * 8;
                uint32 off = sw128((uint32)(kr * 128 + nn * 2));
                uint32 Vh[4], Vl[4];
                ldsm4t(stb + VH_ + off, Vh);
                ldsm4t(stb + VL_ + off, Vl);
                #pragma unroll
                for (int mi = 0; mi < 2; mi++)
                    #pragma unroll
                    for (int j = 0; j < 2; j++) {
                        float* oo = o[mi][njp * 2 + j];
                        mma16816(oo, aPh[mi][kc], Vh[2*j], Vh[2*j+1]);
                        mma16816(oo, aPh[mi][kc], Vl[2*j], Vl[2*j+1]);
                        mma16816(oo, aPl[mi][kc], Vh[2*j], Vh[2*j+1]);
                    }
            }
    }

    // ---- reductions & store ----
    #pragma unroll
    for (int mi = 0; mi < 2; mi++)
        #pragma unroll
        for (int h = 0; h < 2; h++) {
            float v = lsum[mi][h];
            v += __shfl_xor_sync(0xffffffffu, v, 1);
            v += __shfl_xor_sync(0xffffffffu, v, 2);
            lsum[mi][h] = v;
        }

    __syncthreads();
    float* Obuf = reinterpret_cast<float*>(smem + AOB);
    float* lbuf = reinterpret_cast<float*>(smem + ALB);

    if (t == 0) {
        #pragma unroll
        for (int mi = 0; mi < 2; mi++)
            #pragma unroll
            for (int h = 0; h < 2; h++)
                lbuf[wk * 128 + wm * 32 + mi * 16 + h * 8 + g] = lsum[mi][h];
    }
    if (wk == 1) {
        #pragma unroll
        for (int mi = 0; mi < 2; mi++)
            #pragma unroll
            for (int nj = 0; nj < 8; nj++) {
                int r0 = wm * 32 + mi * 16 + g;
                int col = nj * 8 + 2 * t;
                *reinterpret_cast<float2*>(&Obuf[r0 * 66 + col])
                    = make_float2(o[mi][nj][0], o[mi][nj][1]);
                *reinterpret_cast<float2*>(&Obuf[(r0 + 8) * 66 + col])
                    = make_float2(o[mi][nj][2], o[mi][nj][3]);
            }
    }
    __syncthreads();

    const size_t qbase = (size_t)b * NT + (size_t)qi * 128;
    if (wk == 0) {
        float* op = g_opart[s];
        #pragma unroll
        for (int mi = 0; mi < 2; mi++)
            #pragma unroll
            for (int nj = 0; nj < 8; nj++) {
                int r0 = wm * 32 + mi * 16 + g;
                int col = nj * 8 + 2 * t;
                float2 u0 = *reinterpret_cast<float2*>(&Obuf[r0 * 66 + col]);
                float2 u1 = *reinterpret_cast<float2*>(&Obuf[(r0 + 8) * 66 + col]);
                *reinterpret_cast<float2*>(&op[(qbase + r0) * 64 + col])
                    = make_float2(o[mi][nj][0] + u0.x, o[mi][nj][1] + u0.y);
                *reinterpret_cast<float2*>(&op[(qbase + r0 + 8) * 64 + col])
                    = make_float2(o[mi][nj][2] + u1.x, o[mi][nj][3] + u1.y);
            }
    }
    if (tid < 128)
        g_lpart[s][qbase + tid] = lbuf[tid] + lbuf[128 + tid];
}

// ===========================================================================
// Combine: out = (O0 [+ O1]) / (l0 [+ l1])
// ===========================================================================
__global__ __launch_bounds__(256) void combine_kernel(float* __restrict__ out)
{
    int f = blockIdx.x * 256 + threadIdx.x;
    int row = f >> 4;
    int qi = (row & (NT - 1)) >> 7;
    float l = g_lpart[0][row];
    float4 o = reinterpret_cast<const float4*>(g_opart[0])[f];
    if (qi >= 8) {
        l += g_lpart[1][row];
        float4 o1 = reinterpret_cast<const float4*>(g_opart[1])[f];
        o.x += o1.x; o.y += o1.y; o.z += o1.z; o.w += o1.w;
    }
    float inv = 1.0f / l;
    o.x *= inv; o.y *= inv; o.z *= inv; o.w *= inv;
    reinterpret_cast<float4*>(out)[f] = o;
}

// ===========================================================================
extern "C" void kernel_launch(void* const* d_in, const int* in_sizes, int n_in,
                              void* d_out, int out_size)
{
    const float* x  = (const float*)d_in[0];
    const float* Wk = (const float*)d_in[1];
    const float* Wq = (const float*)d_in[2];
    const float* Wv = (const float*)d_in[3];
    float* out = (float*)d_out;

    static bool attr_done = false;
    if (!attr_done) {
        cudaFuncSetAttribute(qkv_kernel,  cudaFuncAttributeMaxDynamicSharedMemorySize, QKV_SMEM);
        cudaFuncSetAttribute(attn_kernel, cudaFuncAttributeMaxDynamicSharedMemorySize, ATTN_SMEM);
        attr_done = true;
    }

    wsplit_kernel<<<288, 256>>>(Wk, Wq, Wv);
    qkv_kernel<<<BT / 128, 256, QKV_SMEM>>>(x);
    attn_kernel<<<192, 256, ATTN_SMEM>>>();
    combine_kernel<<<(BT * HS / 4) / 256, 256>>>(out);
}

// round 5
// speedup vs baseline: 3.8635x; 1.0045x over previous
#include <cuda_runtime.h>
#include <cuda_bf16.h>

#define NB 8
#define NT 2048
#define NC 768
#define HS 64
#define BT (NB*NT)
// log2(e) / sqrt(768)
#define SL2E 0.0520587735f

typedef unsigned int uint32;

// ---------------- global scratch (allocation-free rule) ----------------
__device__ __align__(16) __nv_bfloat16 g_qh[BT*HS], g_ql[BT*HS];
__device__ __align__(16) __nv_bfloat16 g_kh[BT*HS], g_kl[BT*HS];
__device__ __align__(16) __nv_bfloat16 g_vh[BT*HS], g_vl[BT*HS];
__device__ __align__(16) uint32 g_wh[768*96], g_wl[768*96];   // W^T pre-split
__device__ __align__(16) float g_opart[4][BT*HS];
__device__ float g_lpart[4][BT];

// ---------------- helpers ----------------
__device__ __forceinline__ uint32 smem_u32(const void* p) {
    uint32 a;
    asm("{ .reg .u64 t; cvta.to.shared.u64 t, %1; cvt.u32.u64 %0, t; }" : "=r"(a) : "l"(p));
    return a;
}
__device__ __forceinline__ uint32 sw128(uint32 off) { return off ^ ((off >> 3) & 0x70); }

__device__ __forceinline__ void ldsm4(uint32 addr, uint32* r) {
    asm volatile("ldmatrix.sync.aligned.m8n8.x4.shared.b16 {%0,%1,%2,%3}, [%4];"
                 : "=r"(r[0]), "=r"(r[1]), "=r"(r[2]), "=r"(r[3]) : "r"(addr));
}
__device__ __forceinline__ void ldsm4t(uint32 addr, uint32* r) {
    asm volatile("ldmatrix.sync.aligned.m8n8.x4.trans.shared.b16 {%0,%1,%2,%3}, [%4];"
                 : "=r"(r[0]), "=r"(r[1]), "=r"(r[2]), "=r"(r[3]) : "r"(addr));
}
__device__ __forceinline__ void mma16816(float* c, const uint32* a, uint32 b0, uint32 b1) {
    asm volatile("mma.sync.aligned.m16n8k16.row.col.f32.bf16.bf16.f32 "
                 "{%0,%1,%2,%3}, {%4,%5,%6,%7}, {%8,%9}, {%0,%1,%2,%3};"
                 : "+f"(c[0]), "+f"(c[1]), "+f"(c[2]), "+f"(c[3])
                 : "r"(a[0]), "r"(a[1]), "r"(a[2]), "r"(a[3]), "r"(b0), "r"(b1));
}
__device__ __forceinline__ float ex2(float x) {
    float y; asm("ex2.approx.ftz.f32 %0, %1;" : "=f"(y) : "f"(x)); return y;
}
__device__ __forceinline__ void split2(float a, float b, uint32& hw, uint32& lw) {
    __nv_bfloat162 h2 = __floats2bfloat162_rn(a, b);
    float ra = a - __bfloat162float(h2.x);
    float rb = b - __bfloat162float(h2.y);
    __nv_bfloat162 l2 = __floats2bfloat162_rn(ra, rb);
    hw = *reinterpret_cast<uint32*>(&h2);
    lw = *reinterpret_cast<uint32*>(&l2);
}
#define CP_ASYNC16(dst, src) \
    asm volatile("cp.async.cg.shared.global [%0], [%1], 16;" :: "r"(dst), "l"(src) : "memory")
#define CP_COMMIT asm volatile("cp.async.commit_group;" ::: "memory")
#define CP_WAIT0  asm volatile("cp.async.wait_group 0;" ::: "memory")

// ===========================================================================
// W pre-split
// ===========================================================================
__global__ __launch_bounds__(256) void wsplit_kernel(
    const float* __restrict__ Wk, const float* __restrict__ Wq, const float* __restrict__ Wv)
{
    int i = blockIdx.x * 256 + threadIdx.x;
    int k = i / 96, p = i % 96;
    int n0 = p * 2;
    const float* W = (n0 < 64) ? Wq : (n0 < 128 ? Wk : Wv);
    int nc = n0 & 63;
    float a = W[(size_t)k * HS + nc], b = W[(size_t)k * HS + nc + 1];
    uint32 hw, lw;
    split2(a, b, hw, lw);
    g_wh[i] = hw; g_wl[i] = lw;
}

// ===========================================================================
// QKV (unchanged from R4): per CTA 128x192, bf16x3, 2-stage pipeline
// ===========================================================================
#define XH 0
#define XL 16384
#define WH 32768
#define WL 58368
#define QSTG 83968
#define QKV_SMEM (2*QSTG)

__global__ __launch_bounds__(256, 1) void qkv_kernel(const float* __restrict__ x)
{
    extern __shared__ char smem[];
    const uint32 sb = smem_u32(smem);
    const int tid = threadIdx.x;
    const int wid = tid >> 5, lane = tid & 31;
    const int wm = wid & 3, wn = wid >> 2;
    const int row0 = blockIdx.x * 128;

    float c[2][12][4];
    #pragma unroll
    for (int mi = 0; mi < 2; mi++)
        #pragma unroll
        for (int nj = 0; nj < 12; nj++)
            #pragma unroll
            for (int e = 0; e < 4; e++) c[mi][nj][e] = 0.f;

    float4 rx[4][2];

    {
        const int k0 = 0;
        #pragma unroll
        for (int i = 0; i < 4; i++) {
            int f = tid + i * 256, r = f >> 3, g8 = (f & 7) * 8;
            const float* src = x + (size_t)(row0 + r) * NC + k0 + g8;
            rx[i][0] = *reinterpret_cast<const float4*>(src);
            rx[i][1] = *reinterpret_cast<const float4*>(src + 4);
        }
        #pragma unroll
        for (int i = 0; i < 6; i++) {
            int f = tid + i * 256, kk = f / 24, cc = f % 24;
            CP_ASYNC16(sb + WH + kk * 400 + cc * 16, &g_wh[(size_t)(k0 + kk) * 96 + cc * 4]);
            CP_ASYNC16(sb + WL + kk * 400 + cc * 16, &g_wl[(size_t)(k0 + kk) * 96 + cc * 4]);
        }
        CP_COMMIT;
        #pragma unroll
        for (int i = 0; i < 4; i++) {
            int f = tid + i * 256, r = f >> 3, g8 = (f & 7) * 8;
            uint32 h0, l0, h1, l1, h2, l2, h3, l3;
            split2(rx[i][0].x, rx[i][0].y, h0, l0); split2(rx[i][0].z, rx[i][0].w, h1, l1);
            split2(rx[i][1].x, rx[i][1].y, h2, l2); split2(rx[i][1].z, rx[i][1].w, h3, l3);
            uint32 off = sw128((uint32)(r * 128 + g8 * 2));
            *reinterpret_cast<uint4*>(smem + XH + off) = make_uint4(h0, h1, h2, h3);
            *reinterpret_cast<uint4*>(smem + XL + off) = make_uint4(l0, l1, l2, l3);
        }
    }

    for (int kc = 0; kc < 12; kc++) {
        const uint32 stb = sb + (kc & 1) * QSTG;
        char* nxt = smem + ((kc + 1) & 1) * QSTG;
        const uint32 stbn = sb + ((kc + 1) & 1) * QSTG;

        CP_WAIT0;
        __syncthreads();

        if (kc < 11) {
            const int k0 = (kc + 1) * 64;
            #pragma unroll
            for (int i = 0; i < 4; i++) {
                int f = tid + i * 256, r = f >> 3, g8 = (f & 7) * 8;
                const float* src = x + (size_t)(row0 + r) * NC + k0 + g8;
                rx[i][0] = *reinterpret_cast<const float4*>(src);
                rx[i][1] = *reinterpret_cast<const float4*>(src + 4);
            }
            #pragma unroll
            for (int i = 0; i < 6; i++) {
                int f = tid + i * 256, kk = f / 24, cc = f % 24;
                CP_ASYNC16(stbn + WH + kk * 400 + cc * 16, &g_wh[(size_t)(k0 + kk) * 96 + cc * 4]);
                CP_ASYNC16(stbn + WL + kk * 400 + cc * 16, &g_wl[(size_t)(k0 + kk) * 96 + cc * 4]);
            }
            CP_COMMIT;
        }

        #pragma unroll
        for (int ks = 0; ks < 4; ks++) {
            uint32 Ah[2][4], Al[2][4];
            #pragma unroll
            for (int mi = 0; mi < 2; mi++) {
                uint32 off = sw128((uint32)((wm * 32 + mi * 16 + (lane & 15)) * 128
                                            + ks * 32 + (lane >> 4) * 16));
                ldsm4(stb + XH + off, Ah[mi]);
                ldsm4(stb + XL + off, Al[mi]);
            }
            #pragma unroll
            for (int njp = 0; njp < 6; njp++) {
                int nabs = wn * 96 + njp * 16 + ((lane >> 4) & 1) * 8;
                int kl_ = ks * 16 + (lane & 15);
                uint32 boff = (uint32)(kl_ * 400 + nabs * 2);
                uint32 Bh[4], Bl[4];
                ldsm4t(stb + WH + boff, Bh);
                ldsm4t(stb + WL + boff, Bl);
                #pragma unroll
                for (int mi = 0; mi < 2; mi++)
                    #pragma unroll
                    for (int j = 0; j < 2; j++) {
                        float* cc = c[mi][njp * 2 + j];
                        mma16816(cc, Ah[mi], Bh[2*j], Bh[2*j+1]);
                        mma16816(cc, Ah[mi], Bl[2*j], Bl[2*j+1]);
                        mma16816(cc, Al[mi], Bh[2*j], Bh[2*j+1]);
                    }
            }
        }

        if (kc < 11) {
            #pragma unroll
            for (int i = 0; i < 4; i++) {
                int f = tid + i * 256, r = f >> 3, g8 = (f & 7) * 8;
                uint32 h0, l0, h1, l1, h2, l2, h3, l3;
                split2(rx[i][0].x, rx[i][0].y, h0, l0); split2(rx[i][0].z, rx[i][0].w, h1, l1);
                split2(rx[i][1].x, rx[i][1].y, h2, l2); split2(rx[i][1].z, rx[i][1].w, h3, l3);
                uint32 off = sw128((uint32)(r * 128 + g8 * 2));
                *reinterpret_cast<uint4*>(nxt + XH + off) = make_uint4(h0, h1, h2, h3);
                *reinterpret_cast<uint4*>(nxt + XL + off) = make_uint4(l0, l1, l2, l3);
            }
        }
    }

    const int g = lane >> 2, t = lane & 3;
    uint32* gqh = reinterpret_cast<uint32*>(g_qh);
    uint32* gql = reinterpret_cast<uint32*>(g_ql);
    uint32* gkh = reinterpret_cast<uint32*>(g_kh);
    uint32* gkl = reinterpret_cast<uint32*>(g_kl);
    uint32* gvh = reinterpret_cast<uint32*>(g_vh);
    uint32* gvl = reinterpret_cast<uint32*>(g_vl);
    #pragma unroll
    for (int mi = 0; mi < 2; mi++)
        #pragma unroll
        for (int nj = 0; nj < 12; nj++)
            #pragma unroll
            for (int h = 0; h < 2; h++) {
                size_t row = (size_t)(row0 + wm * 32 + mi * 16 + h * 8 + g);
                int colp = wn * 48 + nj * 4 + t;
                float v0 = c[mi][nj][h * 2], v1 = c[mi][nj][h * 2 + 1];
                if (colp < 32) { v0 *= SL2E; v1 *= SL2E; }
                uint32 hw, lw;
                split2(v0, v1, hw, lw);
                if (colp < 32)      { gqh[row * 32 + colp]      = hw; gql[row * 32 + colp]      = lw; }
                else if (colp < 64) { gkh[row * 32 + colp - 32] = hw; gkl[row * 32 + colp - 32] = lw; }
                else                { gvh[row * 32 + colp - 64] = hw; gvl[row * 32 + colp - 64] = lw; }
            }
}

// ===========================================================================
// Attention: 320 units, 64-key tiles, 96KB smem, 2 CTAs/SM target.
// warp = 32 q-rows (wm) x 32 keys (wk).
// ===========================================================================
#define AQH 0
#define AQL 16384
#define AST 32768
#define STG 32768
#define KH_ 0
#define KL_ 8192
#define VH_ 16384
#define VL_ 24576
#define AOB 32768
#define ALB 66560
#define ATTN_SMEM (AST + 2*STG)

__device__ __forceinline__ void stage_kv_async(uint32 dstb, int b, int jt, int tid)
{
    const uint32* gkh = reinterpret_cast<const uint32*>(g_kh);
    const uint32* gkl = reinterpret_cast<const uint32*>(g_kl);
    const uint32* gvh = reinterpret_cast<const uint32*>(g_vh);
    const uint32* gvl = reinterpret_cast<const uint32*>(g_vl);
    size_t base = ((size_t)b * NT + (size_t)jt * 64) * 32;
    #pragma unroll
    for (int i = 0; i < 2; i++) {
        int f = tid + i * 256;              // 512 16B-chunks per array
        int r = f >> 3, c16 = f & 7;
        uint32 off = sw128((uint32)(r * 128 + c16 * 16));
        size_t gidx = base + r * 32 + c16 * 4;
        CP_ASYNC16(dstb + KH_ + off, gkh + gidx);
        CP_ASYNC16(dstb + KL_ + off, gkl + gidx);
        CP_ASYNC16(dstb + VH_ + off, gvh + gidx);
        CP_ASYNC16(dstb + VL_ + off, gvl + gidx);
    }
}

__global__ __launch_bounds__(256, 2) void attn_kernel()
{
    extern __shared__ char smem[];
    const uint32 sb = smem_u32(smem);
    const int tid = threadIdx.x;
    const int wid = tid >> 5, lane = tid & 31;
    const int wm = wid & 3, wk = wid >> 2;
    const int g = lane >> 2, t = lane & 3;

    // unit decode: 40 units/batch, heavy-first
    const int uid = blockIdx.x;
    const int b = uid & 7;
    const int u = 39 - (uid >> 3);
    int qi, s, ns;
    if (u < 4)       { qi = u;                s = 0;           ns = 1; }
    else if (u < 12) { qi = 4 + ((u - 4) >> 1); s = (u - 4) & 1; ns = 2; }
    else if (u < 24) { qi = 8 + (u - 12) / 3; s = (u - 12) % 3; ns = 3; }
    else             { qi = 12 + ((u - 24) >> 2); s = (u - 24) & 3; ns = 4; }
    const int cnt = qi + 1;
    const int kb = 2 * (s * cnt / ns);
    const int ke = 2 * ((s + 1) * cnt / ns);

    // prologue
    stage_kv_async(sb + AST, b, kb, tid);
    CP_COMMIT;
    {
        const uint32* gqh = reinterpret_cast<const uint32*>(g_qh);
        const uint32* gql = reinterpret_cast<const uint32*>(g_ql);
        size_t base = ((size_t)b * NT + (size_t)qi * 128) * 32;
        for (int f = tid; f < 4096; f += 256) {
            int r = f >> 5, cw = f & 31;
            uint32 off = sw128((uint32)(r * 128 + cw * 4));
            *reinterpret_cast<uint32*>(smem + AQH + off) = gqh[base + r * 32 + cw];
            *reinterpret_cast<uint32*>(smem + AQL + off) = gql[base + r * 32 + cw];
        }
    }

    float o[2][8][4];
    float lsum[2][2];
    #pragma unroll
    for (int mi = 0; mi < 2; mi++) {
        lsum[mi][0] = 0.f; lsum[mi][1] = 0.f;
        #pragma unroll
        for (int nj = 0; nj < 8; nj++)
            #pragma unroll
            for (int e = 0; e < 4; e++) o[mi][nj][e] = 0.f;
    }

    for (int jt = kb; jt < ke; jt++) {
        const int p = (jt - kb) & 1;
        const uint32 stb = sb + AST + p * STG;

        CP_WAIT0;
        __syncthreads();

        if (jt + 1 < ke) {
            stage_kv_async(sb + AST + (p ^ 1) * STG, b, jt + 1, tid);
            CP_COMMIT;
        }

        // ---- S = Q K^T  (128q x 64k tile; warp: 32q x 32k) ----
        float sS[2][4][4];
        #pragma unroll
        for (int mi = 0; mi < 2; mi++)
            #pragma unroll
            for (int nj = 0; nj < 4; nj++)
                #pragma unroll
                for (int e = 0; e < 4; e++) sS[mi][nj][e] = 0.f;

        #pragma unroll
        for (int ks = 0; ks < 4; ks++) {
            uint32 Qh[2][4], Ql[2][4];
            #pragma unroll
            for (int mi = 0; mi < 2; mi++) {
                uint32 off = sw128((uint32)((wm * 32 + mi * 16 + (lane & 15)) * 128
                                            + ks * 32 + (lane >> 4) * 16));
                ldsm4(sb + AQH + off, Qh[mi]);
                ldsm4(sb + AQL + off, Ql[mi]);
            }
            #pragma unroll
            for (int njp = 0; njp < 2; njp++) {
                int row = wk * 32 + njp * 16 + (lane & 7) + ((lane >> 4) & 1) * 8;
                uint32 off = sw128((uint32)(row * 128 + ks * 32 + ((lane >> 3) & 1) * 16));
                uint32 Kh[4], Kl[4];
                ldsm4(stb + KH_ + off, Kh);
                ldsm4(stb + KL_ + off, Kl);
                #pragma unroll
                for (int mi = 0; mi < 2; mi++)
                    #pragma unroll
                    for (int j = 0; j < 2; j++) {
                        float* cc = sS[mi][njp * 2 + j];
                        mma16816(cc, Qh[mi], Kh[2*j], Kh[2*j+1]);
                        mma16816(cc, Qh[mi], Kl[2*j], Kl[2*j+1]);
                        mma16816(cc, Ql[mi], Kh[2*j], Kh[2*j+1]);
                    }
            }
        }

        // ---- epilogue: mask + exp2 + row-sum ----
        const int kofs = jt * 64 - qi * 128;   // negative for interior tiles
        #pragma unroll
        for (int mi = 0; mi < 2; mi++)
            #pragma unroll
            for (int nj = 0; nj < 4; nj++)
                #pragma unroll
                for (int e = 0; e < 4; e++) {
                    int rl = wm * 32 + mi * 16 + (e >> 1) * 8 + g;
                    int cl = wk * 32 + nj * 8 + 2 * t + (e & 1);
                    float p2 = (cl + kofs > rl) ? 0.f : ex2(sS[mi][nj][e]);
                    sS[mi][nj][e] = p2;
                    lsum[mi][e >> 1] += p2;
                }

        // ---- O += P V (P packed per kc-group to limit registers) ----
        #pragma unroll
        for (int kc = 0; kc < 2; kc++) {
            uint32 aPh[2][4], aPl[2][4];
            #pragma unroll
            for (int mi = 0; mi < 2; mi++) {
                split2(sS[mi][2*kc][0],   sS[mi][2*kc][1],   aPh[mi][0], aPl[mi][0]);
                split2(sS[mi][2*kc][2],   sS[mi][2*kc][3],   aPh[mi][1], aPl[mi][1]);
                split2(sS[mi][2*kc+1][0], sS[mi][2*kc+1][1], aPh[mi][2], aPl[mi][2]);
                split2(sS[mi][2*kc+1][2], sS[mi][2*kc+1][3], aPh[mi][3], aPl[mi][3]);
            }
            #pragma unroll
            for (int njp = 0; njp < 4; njp++) {
                int kr = wk * 32 + kc * 16 + (lane & 15);
                int nn = njp * 16 + ((lane >> 4) & 1) * 8;
                uint32 off = sw128((uint32)(kr * 128 + nn * 2));
                uint32 Vh[4], Vl[4];
                ldsm4t(stb + VH_ + off, Vh);
                ldsm4t(stb + VL_ + off, Vl);
                #pragma unroll
                for (int mi = 0; mi < 2; mi++)
                    #pragma unroll
                    for (int j = 0; j < 2; j++) {
                        float* oo = o[mi][njp * 2 + j];
                        mma16816(oo, aPh[mi], Vh[2*j], Vh[2*j+1]);
                        mma16816(oo, aPh[mi], Vl[2*j], Vl[2*j+1]);
                        mma16816(oo, aPl[mi], Vh[2*j], Vh[2*j+1]);
                    }
            }
        }
    }

    // ---- reductions & store ----
    #pragma unroll
    for (int mi = 0; mi < 2; mi++)
        #pragma unroll
        for (int h = 0; h < 2; h++) {
            float v = lsum[mi][h];
            v += __shfl_xor_sync(0xffffffffu, v, 1);
            v += __shfl_xor_sync(0xffffffffu, v, 2);
            lsum[mi][h] = v;
        }

    __syncthreads();
    float* Obuf = reinterpret_cast<float*>(smem + AOB);
    float* lbuf = reinterpret_cast<float*>(smem + ALB);

    if (t == 0) {
        #pragma unroll
        for (int mi = 0; mi < 2; mi++)
            #pragma unroll
            for (int h = 0; h < 2; h++)
                lbuf[wk * 128 + wm * 32 + mi * 16 + h * 8 + g] = lsum[mi][h];
    }
    if (wk == 1) {
        #pragma unroll
        for (int mi = 0; mi < 2; mi++)
            #pragma unroll
            for (int nj = 0; nj < 8; nj++) {
                int r0 = wm * 32 + mi * 16 + g;
                int col = nj * 8 + 2 * t;
                *reinterpret_cast<float2*>(&Obuf[r0 * 66 + col])
                    = make_float2(o[mi][nj][0], o[mi][nj][1]);
                *reinterpret_cast<float2*>(&Obuf[(r0 + 8) * 66 + col])
                    = make_float2(o[mi][nj][2], o[mi][nj][3]);
            }
    }
    __syncthreads();

    const size_t qbase = (size_t)b * NT + (size_t)qi * 128;
    if (wk == 0) {
        float* op = g_opart[s];
        #pragma unroll
        for (int mi = 0; mi < 2; mi++)
            #pragma unroll
            for (int nj = 0; nj < 8; nj++) {
                int r0 = wm * 32 + mi * 16 + g;
                int col = nj * 8 + 2 * t;
                float2 u0 = *reinterpret_cast<float2*>(&Obuf[r0 * 66 + col]);
                float2 u1 = *reinterpret_cast<float2*>(&Obuf[(r0 + 8) * 66 + col]);
                *reinterpret_cast<float2*>(&op[(qbase + r0) * 64 + col])
                    = make_float2(o[mi][nj][0] + u0.x, o[mi][nj][1] + u0.y);
                *reinterpret_cast<float2*>(&op[(qbase + r0 + 8) * 64 + col])
                    = make_float2(o[mi][nj][2] + u1.x, o[mi][nj][3] + u1.y);
            }
    }
    if (tid < 128)
        g_lpart[s][qbase + tid] = lbuf[tid] + lbuf[128 + tid];
}

// ===========================================================================
// Combine: out = sum_s O_s / sum_s l_s    (ns = qi/4 + 1)
// ===========================================================================
__global__ __launch_bounds__(256) void combine_kernel(float* __restrict__ out)
{
    int f = blockIdx.x * 256 + threadIdx.x;
    int row = f >> 4;
    int qi = (row & (NT - 1)) >> 7;
    int ns = (qi >> 2) + 1;
    float l = 0.f;
    float4 o = make_float4(0.f, 0.f, 0.f, 0.f);
    for (int s = 0; s < ns; s++) {
        l += g_lpart[s][row];
        float4 t = reinterpret_cast<const float4*>(g_opart[s])[f];
        o.x += t.x; o.y += t.y; o.z += t.z; o.w += t.w;
    }
    float inv = 1.0f / l;
    o.x *= inv; o.y *= inv; o.z *= inv; o.w *= inv;
    reinterpret_cast<float4*>(out)[f] = o;
}

// ===========================================================================
extern "C" void kernel_launch(void* const* d_in, const int* in_sizes, int n_in,
                              void* d_out, int out_size)
{
    const float* x  = (const float*)d_in[0];
    const float* Wk = (const float*)d_in[1];
    const float* Wq = (const float*)d_in[2];
    const float* Wv = (const float*)d_in[3];
    float* out = (float*)d_out;

    static bool attr_done = false;
    if (!attr_done) {
        cudaFuncSetAttribute(qkv_kernel,  cudaFuncAttributeMaxDynamicSharedMemorySize, QKV_SMEM);
        cudaFuncSetAttribute(attn_kernel, cudaFuncAttributeMaxDynamicSharedMemorySize, ATTN_SMEM);
        attr_done = true;
    }

    wsplit_kernel<<<288, 256>>>(Wk, Wq, Wv);
    qkv_kernel<<<BT / 128, 256, QKV_SMEM>>>(x);
    attn_kernel<<<320, 256, ATTN_SMEM>>>();
    combine_kernel<<<(BT * HS / 4) / 256, 256>>>(out);
}